// round 1
// baseline (speedup 1.0000x reference)
#include <cuda_runtime.h>
#include <cstdint>

typedef unsigned long long ull;

#define NB   32
#define SEQ  2048
#define NI   256
#define NH   256
#define NG   1024   // 4*NH, gate order [f, i, c, o]

// Scratch: xg[b][s][g] fp32 (256 MB) — __device__ global, no allocation.
__device__ float g_xg[(size_t)NB * SEQ * NG];

// ---------------- f32x2 helpers (full-rate FMA path on sm_103a) ----------------
__device__ __forceinline__ ull pack2(float lo, float hi) {
    ull r;
    asm("mov.b64 %0, {%1, %2};" : "=l"(r) : "f"(lo), "f"(hi));
    return r;
}
__device__ __forceinline__ ull dup2(float v) {
    ull r;
    asm("mov.b64 %0, {%1, %1};" : "=l"(r) : "f"(v));
    return r;
}
__device__ __forceinline__ void fma2(ull& acc, ull a, ull b) {
    asm("fma.rn.f32x2 %0, %1, %2, %0;" : "+l"(acc) : "l"(a), "l"(b));
}
__device__ __forceinline__ float lo2(ull v) { return __uint_as_float((unsigned)v); }
__device__ __forceinline__ float hi2(ull v) { return __uint_as_float((unsigned)(v >> 32)); }

// Fast, accurate-enough activations (fp32, err ~1e-7)
__device__ __forceinline__ float sigmoidf_fast(float x) {
    float e = __expf(-x);
    return __fdividef(1.0f, 1.0f + e);
}
__device__ __forceinline__ float tanhf_fast(float x) {
    float e = __expf(-2.0f * x);
    return __fdividef(2.0f, 1.0f + e) - 1.0f;
}

// =============================================================================
// Phase 1: xg[m, n] = x[m, :] @ Wcat[:, n] + bcat[n]
//   M = 65536 (b*2048+s), K = 256, N = 1024.  128x128 tiles, 256 threads,
//   8x8 micro-tile with packed f32x2 FMAs, register-staged K pipeline.
// =============================================================================
#define BM 128
#define BN 128
#define BK 16

__global__ __launch_bounds__(256, 2) void xw_gemm(
    const float* __restrict__ x,
    const float* __restrict__ W0, const float* __restrict__ W1,
    const float* __restrict__ W2, const float* __restrict__ W3,
    const float* __restrict__ b0, const float* __restrict__ b1,
    const float* __restrict__ b2, const float* __restrict__ b3)
{
    __shared__ float As[BK][BM];   // transposed A tile: As[k][m]
    __shared__ float Bs[BK][BN];   // Bs[k][n]

    const int tid = threadIdx.x;
    const int m0  = blockIdx.x * BM;
    const int nb  = blockIdx.y;          // 0..7 (each n-tile within one gate)
    const int gate = nb >> 1;
    const float* W  = (gate == 0) ? W0 : (gate == 1) ? W1 : (gate == 2) ? W2 : W3;
    const float* bv = (gate == 0) ? b0 : (gate == 1) ? b1 : (gate == 2) ? b2 : b3;
    const int colbase = (nb & 1) * 128;  // column offset within the gate

    const int ty = tid >> 4;             // 0..15
    const int tx = tid & 15;             // 0..15

    ull acc[8][4];
    #pragma unroll
    for (int i = 0; i < 8; i++)
        #pragma unroll
        for (int j = 0; j < 4; j++) acc[i][j] = 0ull;

    // Load-index precompute
    const int fa0 = tid, fa1 = tid + 256;          // A: 512 float4 per chunk
    const int arow0 = fa0 >> 2, akc0 = fa0 & 3;
    const int arow1 = fa1 >> 2, akc1 = fa1 & 3;
    const int bkr0 = fa0 >> 5, bnq0 = fa0 & 31;    // B: 512 float4 per chunk
    const int bkr1 = fa1 >> 5, bnq1 = fa1 & 31;

    float4 aReg0, aReg1, bReg0, bReg1;

    // Prologue: chunk 0 -> smem
    aReg0 = *(const float4*)&x[(size_t)(m0 + arow0) * NI + akc0 * 4];
    aReg1 = *(const float4*)&x[(size_t)(m0 + arow1) * NI + akc1 * 4];
    bReg0 = *(const float4*)&W[(size_t)bkr0 * NH + colbase + bnq0 * 4];
    bReg1 = *(const float4*)&W[(size_t)bkr1 * NH + colbase + bnq1 * 4];
    As[akc0*4+0][arow0] = aReg0.x; As[akc0*4+1][arow0] = aReg0.y;
    As[akc0*4+2][arow0] = aReg0.z; As[akc0*4+3][arow0] = aReg0.w;
    As[akc1*4+0][arow1] = aReg1.x; As[akc1*4+1][arow1] = aReg1.y;
    As[akc1*4+2][arow1] = aReg1.z; As[akc1*4+3][arow1] = aReg1.w;
    *(float4*)&Bs[bkr0][bnq0 * 4] = bReg0;
    *(float4*)&Bs[bkr1][bnq1 * 4] = bReg1;
    __syncthreads();

    const int NCHUNK = NI / BK;   // 16
    for (int kb = 0; kb < NCHUNK; kb++) {
        if (kb + 1 < NCHUNK) {
            const int kofs = (kb + 1) * BK;
            aReg0 = *(const float4*)&x[(size_t)(m0 + arow0) * NI + kofs + akc0 * 4];
            aReg1 = *(const float4*)&x[(size_t)(m0 + arow1) * NI + kofs + akc1 * 4];
            bReg0 = *(const float4*)&W[(size_t)(kofs + bkr0) * NH + colbase + bnq0 * 4];
            bReg1 = *(const float4*)&W[(size_t)(kofs + bkr1) * NH + colbase + bnq1 * 4];
        }
        #pragma unroll
        for (int k = 0; k < BK; k++) {
            float4 a0 = *(const float4*)&As[k][ty * 8];
            float4 a1 = *(const float4*)&As[k][ty * 8 + 4];
            ulonglong2 bp0 = *(const ulonglong2*)&Bs[k][tx * 8];
            ulonglong2 bp1 = *(const ulonglong2*)&Bs[k][tx * 8 + 4];
            float av[8] = {a0.x, a0.y, a0.z, a0.w, a1.x, a1.y, a1.z, a1.w};
            #pragma unroll
            for (int i = 0; i < 8; i++) {
                ull ad = dup2(av[i]);
                fma2(acc[i][0], ad, bp0.x);
                fma2(acc[i][1], ad, bp0.y);
                fma2(acc[i][2], ad, bp1.x);
                fma2(acc[i][3], ad, bp1.y);
            }
        }
        __syncthreads();
        if (kb + 1 < NCHUNK) {
            As[akc0*4+0][arow0] = aReg0.x; As[akc0*4+1][arow0] = aReg0.y;
            As[akc0*4+2][arow0] = aReg0.z; As[akc0*4+3][arow0] = aReg0.w;
            As[akc1*4+0][arow1] = aReg1.x; As[akc1*4+1][arow1] = aReg1.y;
            As[akc1*4+2][arow1] = aReg1.z; As[akc1*4+3][arow1] = aReg1.w;
            *(float4*)&Bs[bkr0][bnq0 * 4] = bReg0;
            *(float4*)&Bs[bkr1][bnq1 * 4] = bReg1;
            __syncthreads();
        }
    }

    // Epilogue: + bias, store to g_xg
    const int ncol0 = colbase + tx * 8;        // within gate
    const int ng0   = gate * 256 + ncol0;      // global gate column
    float bias[8];
    #pragma unroll
    for (int j = 0; j < 8; j++) bias[j] = __ldg(&bv[ncol0 + j]);
    #pragma unroll
    for (int i = 0; i < 8; i++) {
        const int m = m0 + ty * 8 + i;
        float v0 = lo2(acc[i][0]) + bias[0], v1 = hi2(acc[i][0]) + bias[1];
        float v2 = lo2(acc[i][1]) + bias[2], v3 = hi2(acc[i][1]) + bias[3];
        float v4 = lo2(acc[i][2]) + bias[4], v5 = hi2(acc[i][2]) + bias[5];
        float v6 = lo2(acc[i][3]) + bias[6], v7 = hi2(acc[i][3]) + bias[7];
        *(float4*)&g_xg[(size_t)m * NG + ng0]     = make_float4(v0, v1, v2, v3);
        *(float4*)&g_xg[(size_t)m * NG + ng0 + 4] = make_float4(v4, v5, v6, v7);
    }
}

// =============================================================================
// Phase 2: persistent clustered recurrence.
//   16 clusters x 8 CTAs (=128 CTAs, all resident). Cluster c handles batches
//   2c, 2c+1. CTA rank r owns hidden units [32r, 32r+32) => 128 gate columns.
//   U slice [256k x 128cols] lives ENTIRELY in registers as f32x2 pairs.
//   Per step: reg-resident GEMV (fma.rn.f32x2) -> smem reduce -> activations
//   -> c/h update -> DSMEM broadcast of h to all 8 ranks -> barrier.cluster.
// =============================================================================
#define CLSZ 8
#define P2T  512

__global__ __launch_bounds__(P2T, 1) __cluster_dims__(CLSZ, 1, 1)
void lstm_rec(const float* __restrict__ U0, const float* __restrict__ U1,
              const float* __restrict__ U2, const float* __restrict__ U3,
              float* __restrict__ out, int write_hc)
{
    __shared__ float h_buf[2][2][NH];     // [parity][batch][k]
    __shared__ float red[2][4][128];      // [batch][kq][col]
    __shared__ float zbuf[2][128];        // [batch][col] activated gates

    const int tid = threadIdx.x;
    unsigned rank;
    asm("mov.u32 %0, %%cluster_ctarank;" : "=r"(rank));
    const int cid = blockIdx.x / CLSZ;

    const int c    = tid & 127;           // column within CTA
    const int kq   = tid >> 7;            // k-quarter 0..3
    const int gate = c >> 5;
    const int jl   = c & 31;
    const int j    = (int)rank * 32 + jl; // global hidden unit of this column

    const float* U = (gate == 0) ? U0 : (gate == 1) ? U1 : (gate == 2) ? U2 : U3;

    // Register-resident U slice: 64 floats/thread as 32 packed pairs.
    ull u2[32];
    {
        const float* up = U + (size_t)(kq * 64) * NH + j;
        #pragma unroll
        for (int i = 0; i < 32; i++) {
            float lo = up[(size_t)(2 * i) * NH];
            float hi = up[(size_t)(2 * i + 1) * NH];
            u2[i] = pack2(lo, hi);
        }
    }

    // Zero initial h (parity 0)
    h_buf[0][tid >> 8][tid & 255] = 0.0f;
    __syncthreads();

    float* o_hid = out;
    float* o_ht  = out + (size_t)NB * SEQ * NH;
    float* o_ct  = o_ht + NB * NH;

    // z-thread (tid<256) mapping for xg loads
    const int bz  = (tid >> 7) & 1;           // batch slot for z threads
    const int bgz = cid * 2 + bz;             // global batch
    const int nz  = gate * 256 + j;           // global gate column

    float xg_cur = 0.0f;
    if (tid < 256)
        xg_cur = g_xg[((size_t)bgz * SEQ + 0) * NG + nz];

    // c/h-thread (tid<64) state
    float cstate = 0.0f, hstate = 0.0f;
    const int bh  = tid >> 5;                 // batch slot
    const int jh  = tid & 31;
    const int jgl = (int)rank * 32 + jh;      // global hidden unit
    const int bgh = cid * 2 + bh;             // global batch

    for (int t = 0; t < SEQ; t++) {
        const int pin = t & 1;

        // ---- GEMV: both batches, reg-resident U ----
        #pragma unroll
        for (int b = 0; b < 2; b++) {
            const ulonglong2* h4 = (const ulonglong2*)&h_buf[pin][b][kq * 64];
            ull s0 = 0, s1 = 0, s2 = 0, s3 = 0;
            #pragma unroll
            for (int i = 0; i < 16; i += 2) {
                ulonglong2 hv0 = h4[i];
                fma2(s0, u2[2 * i],     hv0.x);
                fma2(s1, u2[2 * i + 1], hv0.y);
                ulonglong2 hv1 = h4[i + 1];
                fma2(s2, u2[2 * i + 2], hv1.x);
                fma2(s3, u2[2 * i + 3], hv1.y);
            }
            float part = (lo2(s0) + hi2(s0)) + (lo2(s1) + hi2(s1))
                       + (lo2(s2) + hi2(s2)) + (lo2(s3) + hi2(s3));
            red[b][kq][c] = part;
        }
        __syncthreads();

        // ---- z assembly + activation (tid<256), prefetch next xg ----
        float xg_next = 0.0f;
        if (tid < 256) {
            float z = red[bz][0][c] + red[bz][1][c] + red[bz][2][c] + red[bz][3][c]
                    + xg_cur;
            float a = (gate == 2) ? tanhf_fast(z) : sigmoidf_fast(z);
            zbuf[bz][c] = a;
            if (t + 1 < SEQ)
                xg_next = g_xg[((size_t)bgz * SEQ + (t + 1)) * NG + nz];
        }
        __syncthreads();

        // ---- cell/hidden update + broadcast (tid<64) ----
        if (tid < 64) {
            float f  = zbuf[bh][jh];
            float ii = zbuf[bh][32 + jh];
            float g  = zbuf[bh][64 + jh];
            float o  = zbuf[bh][96 + jh];
            cstate = f * cstate + ii * g;
            hstate = o * tanhf_fast(cstate);

            o_hid[((size_t)bgh * SEQ + t) * NH + jgl] = hstate;

            // Broadcast h into every cluster CTA's next-parity buffer.
            const int pout = pin ^ 1;
            uint32_t la = (uint32_t)__cvta_generic_to_shared(&h_buf[pout][bh][jgl]);
            #pragma unroll
            for (int r = 0; r < CLSZ; r++) {
                uint32_t ra;
                asm volatile("mapa.shared::cluster.u32 %0, %1, %2;"
                             : "=r"(ra) : "r"(la), "r"(r));
                asm volatile("st.shared::cluster.f32 [%0], %1;"
                             :: "r"(ra), "f"(hstate) : "memory");
            }
        }

        // ---- cluster barrier (release/acquire covers DSMEM stores) ----
        asm volatile("barrier.cluster.arrive.aligned;" ::: "memory");
        asm volatile("barrier.cluster.wait.aligned;" ::: "memory");

        xg_cur = xg_next;
    }

    if (write_hc && tid < 64) {
        o_ht[(size_t)bgh * NH + jgl] = hstate;
        o_ct[(size_t)bgh * NH + jgl] = cstate;
    }
}

// =============================================================================
extern "C" void kernel_launch(void* const* d_in, const int* in_sizes, int n_in,
                              void* d_out, int out_size)
{
    const float* x  = (const float*)d_in[0];
    const float* Wf = (const float*)d_in[1];
    const float* Uf = (const float*)d_in[2];
    const float* bf = (const float*)d_in[3];
    const float* Wi = (const float*)d_in[4];
    const float* Ui = (const float*)d_in[5];
    const float* bi = (const float*)d_in[6];
    const float* Wo = (const float*)d_in[7];
    const float* Uo = (const float*)d_in[8];
    const float* bo = (const float*)d_in[9];
    const float* Wc = (const float*)d_in[10];
    const float* Uc = (const float*)d_in[11];
    const float* bc = (const float*)d_in[12];

    // Phase 1: xg = x @ [Wf|Wi|Wc|Wo] + [bf|bi|bc|bo]
    dim3 g1(NB * SEQ / BM, NG / BN);   // (512, 8)
    xw_gemm<<<g1, 256>>>(x, Wf, Wi, Wc, Wo, bf, bi, bc, bo);

    // Phase 2: clustered recurrence. Writes hidden_seq [+ h_t, c_t if present].
    int full = (out_size >= (int)((size_t)NB * SEQ * NH + 2 * NB * NH)) ? 1 : 0;
    lstm_rec<<<16 * CLSZ, P2T>>>(Uf, Ui, Uc, Uo, (float*)d_out, full);
}